// round 7
// baseline (speedup 1.0000x reference)
#include <cuda_runtime.h>
#include <cuda_bf16.h>
#include <cstdint>

// out[i,j,o] = sum_h x[i+1,h]*x[j+1,h]*W[o,h] + b[o]
// (diff/W2 term is antisymmetric -> cancels under (P+P^T)/2 symmetrization)
//
// D_o = A_o B^T, A_o = X .* w_o, B = X (512x768 f32)
// fp32 emulated via bf16 hi/lo 3-split on mma.sync m16n8k16.
// Both output channels fused in one CTA (shared B tiles).
// Upper-tri 32x32 tiles (mirror-write), split-K=4 via red.global.add onto
// zeroed buffer (exactly 4 commutative adds per element -> deterministic).

#define HDIM 768
#define KC 64                    // k per chunk (64 bf16 = 128 B rows)
#define KSPLIT 4
#define NKC 3                    // chunks per K-split (12 total / 4)
#define ROW_B 144                // 128 B data + 16 B pad (conflict-free LDSM)
#define TILE_B (32 * ROW_B)      // 4608 B  (32 rows x 64 bf16)
#define NTILE 6                  // A0hi A0lo A1hi A1lo Bhi Blo
#define STAGE_B (NTILE * TILE_B) // 27648 B
#define NSTAGE 2
#define SMEM_TOTAL (NSTAGE * STAGE_B)   // 55296 B -> 4 CTAs/SM
#define OUT_ELEMS (510 * 510 * 2)

// Pre-split bf16 images: 0:A0hi 1:A0lo 2:A1hi 3:A1lo 4:Bhi 5:Blo
__device__ __nv_bfloat16 g_pre[6][512 * HDIM];

// ---------------------------------------------------------------------------
union Pack8 { __nv_bfloat16 h[8]; uint4 v; };

__device__ __forceinline__ void split8(const float* s, uint4& hi, uint4& lo) {
    Pack8 ph, pl;
#pragma unroll
    for (int t = 0; t < 8; t++) {
        __nv_bfloat16 h = __float2bfloat16(s[t]);
        ph.h[t] = h;
        pl.h[t] = __float2bfloat16(s[t] - __bfloat162float(h));
    }
    hi = ph.v; lo = pl.v;
}

__global__ void prep_kernel(const float* __restrict__ x,
                            const float* __restrict__ W,
                            float* __restrict__ out)
{
    int gid = blockIdx.x * blockDim.x + threadIdx.x;

    // Zero output (fp32 reductions accumulate into it); 130050 float4, exact
    if (gid < OUT_ELEMS / 4)
        *(float4*)(out + (size_t)gid * 4) = make_float4(0.f, 0.f, 0.f, 0.f);

    if (gid >= 512 * (HDIM / 8)) return;
    int i  = gid / (HDIM / 8);
    int k0 = (gid % (HDIM / 8)) * 8;

    float4 x0 = *(const float4*)(x + (size_t)i * HDIM + k0);
    float4 x1 = *(const float4*)(x + (size_t)i * HDIM + k0 + 4);
    float4 wa0 = *(const float4*)(W + k0);
    float4 wa1 = *(const float4*)(W + k0 + 4);
    float4 wb0 = *(const float4*)(W + 1536 + k0);
    float4 wb1 = *(const float4*)(W + 1536 + k0 + 4);

    float xs[8] = {x0.x, x0.y, x0.z, x0.w, x1.x, x1.y, x1.z, x1.w};
    float w0[8] = {wa0.x, wa0.y, wa0.z, wa0.w, wa1.x, wa1.y, wa1.z, wa1.w};
    float w1[8] = {wb0.x, wb0.y, wb0.z, wb0.w, wb1.x, wb1.y, wb1.z, wb1.w};
    float a0[8], a1[8];
#pragma unroll
    for (int t = 0; t < 8; t++) { a0[t] = xs[t] * w0[t]; a1[t] = xs[t] * w1[t]; }

    uint4 h, l;
    size_t off = (size_t)i * HDIM + k0;
    split8(a0, h, l);
    *(uint4*)(&g_pre[0][off]) = h;  *(uint4*)(&g_pre[1][off]) = l;
    split8(a1, h, l);
    *(uint4*)(&g_pre[2][off]) = h;  *(uint4*)(&g_pre[3][off]) = l;
    split8(xs, h, l);
    *(uint4*)(&g_pre[4][off]) = h;  *(uint4*)(&g_pre[5][off]) = l;
}

// ---------------------------------------------------------------------------
__device__ __forceinline__ uint32_t smem_u32(const void* p) {
    uint32_t a;
    asm("{ .reg .u64 t; cvta.to.shared.u64 t, %1; cvt.u32.u64 %0, t; }"
        : "=r"(a) : "l"(p));
    return a;
}

__device__ __forceinline__ void cp16(uint32_t dst, const void* src) {
    asm volatile("cp.async.cg.shared.global [%0], [%1], 16;"
                 :: "r"(dst), "l"(src) : "memory");
}

__device__ __forceinline__ void ldsm4(uint32_t* r, uint32_t addr) {
    asm volatile("ldmatrix.sync.aligned.m8n8.x4.shared.b16 {%0,%1,%2,%3}, [%4];"
                 : "=r"(r[0]), "=r"(r[1]), "=r"(r[2]), "=r"(r[3]) : "r"(addr));
}

__device__ __forceinline__ void mma16816(float* c, const uint32_t* a,
                                         uint32_t b0, uint32_t b1) {
    asm volatile(
        "mma.sync.aligned.m16n8k16.row.col.f32.bf16.bf16.f32 "
        "{%0,%1,%2,%3}, {%4,%5,%6,%7}, {%8,%9}, {%0,%1,%2,%3};"
        : "+f"(c[0]), "+f"(c[1]), "+f"(c[2]), "+f"(c[3])
        : "r"(a[0]), "r"(a[1]), "r"(a[2]), "r"(a[3]), "r"(b0), "r"(b1));
}

__device__ __forceinline__ void red_add(float* p, float v) {
    asm volatile("red.global.add.f32 [%0], %1;" :: "l"(p), "f"(v) : "memory");
}

__global__ void __launch_bounds__(128, 4)
pairwise_mma_kernel(const float* __restrict__ bias, float* __restrict__ out)
{
    // Triangular decode: blockIdx.x in [0,136) -> (bi, bj), bj >= bi
    int t = blockIdx.x;
    int bi = 0;
    while (t >= 16 - bi) { t -= 16 - bi; bi++; }
    const int bj = bi + t;
    const int ks = blockIdx.y;          // K split (0..3)

    extern __shared__ __align__(16) char smem[];
    const uint32_t sb = smem_u32(smem);

    const int tid  = threadIdx.x;
    const int wid  = tid >> 5;
    const int lane = tid & 31;
    const int wm = wid >> 1;          // warp row (0..1) of 16
    const int wn = wid & 1;           // warp col (0..1) of 16

    const __nv_bfloat16* src[NTILE];
    src[0] = &g_pre[0][(size_t)(bi * 32) * HDIM];
    src[1] = &g_pre[1][(size_t)(bi * 32) * HDIM];
    src[2] = &g_pre[2][(size_t)(bi * 32) * HDIM];
    src[3] = &g_pre[3][(size_t)(bi * 32) * HDIM];
    src[4] = &g_pre[4][(size_t)(bj * 32) * HDIM];
    src[5] = &g_pre[5][(size_t)(bj * 32) * HDIM];

    const int lrow = tid >> 3;        // 0..15
    const int lc   = tid & 7;         // 16B chunk within 128B row
    const int kc0  = ks * NKC;        // first chunk of this split

    auto issue = [&](int kc, int sl) {
        const uint32_t dbase = sb + sl * STAGE_B + lc * 16;
        const int kcol = (kc0 + kc) * KC + lc * 8;
#pragma unroll
        for (int q = 0; q < NTILE; q++) {
#pragma unroll
            for (int p = 0; p < 2; p++) {
                const int row = lrow + p * 16;
                cp16(dbase + q * TILE_B + row * ROW_B,
                     src[q] + (size_t)row * HDIM + kcol);
            }
        }
    };

    // Per-channel, three independent split chains: 0=hh, 1=hl, 2=lh
    float acc0[3][2][4] = {};
    float acc1[3][2][4] = {};

    const uint32_t arow = (uint32_t)(wm * 16 + (lane & 15)) * ROW_B
                        + ((lane >> 4) << 4);
    const uint32_t brow = (uint32_t)(wn * 16 + (lane & 15)) * ROW_B
                        + ((lane >> 4) << 4);

    auto compute = [&](int sl) {
        const uint32_t tb = sb + sl * STAGE_B;
#pragma unroll
        for (int h = 0; h < 4; h++) {           // four k16 slices of k64
            uint32_t a0h[4], a0l[4], a1h[4], a1l[4], bh[4], bl[4];
            ldsm4(a0h, tb + 0 * TILE_B + arow + h * 32);
            ldsm4(a0l, tb + 1 * TILE_B + arow + h * 32);
            ldsm4(a1h, tb + 2 * TILE_B + arow + h * 32);
            ldsm4(a1l, tb + 3 * TILE_B + arow + h * 32);
            ldsm4(bh,  tb + 4 * TILE_B + brow + h * 32);
            ldsm4(bl,  tb + 5 * TILE_B + brow + h * 32);
#pragma unroll
            for (int nf = 0; nf < 2; nf++) {
                mma16816(acc0[0][nf], a0h, bh[nf], bh[nf + 2]);
                mma16816(acc1[0][nf], a1h, bh[nf], bh[nf + 2]);
                mma16816(acc0[1][nf], a0h, bl[nf], bl[nf + 2]);
                mma16816(acc1[1][nf], a1h, bl[nf], bl[nf + 2]);
                mma16816(acc0[2][nf], a0l, bh[nf], bh[nf + 2]);
                mma16816(acc1[2][nf], a1l, bh[nf], bh[nf + 2]);
            }
        }
    };

    // ---- 2-stage cp.async pipeline over 3 chunks ----
    issue(0, 0);
    asm volatile("cp.async.commit_group;" ::: "memory");
    issue(1, 1);
    asm volatile("cp.async.commit_group;" ::: "memory");

#pragma unroll 1
    for (int kc = 0; kc < NKC; kc++) {
        if (kc < NKC - 1)
            asm volatile("cp.async.wait_group 1;" ::: "memory");
        else
            asm volatile("cp.async.wait_group 0;" ::: "memory");
        __syncthreads();
        compute(kc & 1);
        __syncthreads();
        if (kc + 2 < NKC) {
            issue(kc + 2, kc & 1);
            asm volatile("cp.async.commit_group;" ::: "memory");
        }
    }

    // ---- epilogue: bias/4 per split, crop [1,510], mirror, red.add ----
    const float bv0 = bias[0] * (1.0f / KSPLIT);
    const float bv1 = bias[1] * (1.0f / KSPLIT);
    const int ib = bi * 32 + wm * 16;
    const int jb = bj * 32 + wn * 16;
    const bool mirror = (bi != bj);

#pragma unroll
    for (int nf = 0; nf < 2; nf++) {
#pragma unroll
        for (int r = 0; r < 4; r++) {
            const int i = ib + (lane >> 2) + ((r >> 1) << 3);
            const int j = jb + nf * 8 + ((lane & 3) << 1) + (r & 1);
            if (i >= 1 && i <= 510 && j >= 1 && j <= 510) {
                const float v0 = acc0[0][nf][r] + acc0[1][nf][r]
                               + acc0[2][nf][r] + bv0;
                const float v1 = acc1[0][nf][r] + acc1[1][nf][r]
                               + acc1[2][nf][r] + bv1;
                float* p = out + ((size_t)(i - 1) * 510 + (j - 1)) * 2;
                red_add(p,     v0);
                red_add(p + 1, v1);
                if (mirror) {
                    float* q = out + ((size_t)(j - 1) * 510 + (i - 1)) * 2;
                    red_add(q,     v0);
                    red_add(q + 1, v1);
                }
            }
        }
    }
}

// ---------------------------------------------------------------------------
extern "C" void kernel_launch(void* const* d_in, const int* in_sizes, int n_in,
                              void* d_out, int out_size)
{
    const float* x = (const float*)d_in[0];   // (1, 512, 768)
    const float* W = (const float*)d_in[1];   // (2, 1536)
    const float* b = (const float*)d_in[2];   // (2,)
    float* out = (float*)d_out;               // (510, 510, 2)

    cudaFuncSetAttribute(pairwise_mma_kernel,
                         cudaFuncAttributeMaxDynamicSharedMemorySize, SMEM_TOTAL);

    prep_kernel<<<(OUT_ELEMS / 4 + 255) / 256, 256>>>(x, W, out);
    pairwise_mma_kernel<<<dim3(136, KSPLIT), 128, SMEM_TOTAL>>>(b, out);
}

// round 8
// speedup vs baseline: 1.0341x; 1.0341x over previous
#include <cuda_runtime.h>
#include <cuda_bf16.h>
#include <cstdint>

// out[i,j,o] = sum_h x[i+1,h]*x[j+1,h]*W[o,h] + b[o]
// (diff/W2 term is antisymmetric -> cancels under (P+P^T)/2 symmetrization)
//
// D_o = A_o B^T, A_o = X .* w_o, B = X (512x768 f32)
// fp32 emulated via bf16 hi/lo 3-split on mma.sync m16n8k16.
// Both channels fused per CTA. Split-K INSIDE the CTA: 2 groups x 4 warps,
// each group half of K with private smem pipeline + group-scoped barriers.
// Partials combined in smem; plain coalesced STG (no atomics anywhere).

#define HDIM 768
#define KC 32                     // k per chunk (32 bf16 = 64 B rows)
#define NKCG 12                   // chunks per group (768 / 32 / 2)
#define ROW_B 80                  // 64 B data + 16 B pad (conflict-free LDSM)
#define TILE_B (32 * ROW_B)       // 2560 B (32 rows x 32 bf16)
#define NTILE 6                   // A0hi A0lo A1hi A1lo Bhi Blo
#define STAGE_B (NTILE * TILE_B)  // 15360 B
#define GRP_B (2 * STAGE_B)       // 30720 B (2 stages)
#define SMEM_TOTAL (2 * GRP_B)    // 61440 B -> 1 CTA/SM
#define PART_OFF GRP_B            // partial buffer reuses group-1 region
#define FIN_STRIDE 66             // final tile row stride in floats (64 + 2 pad)

// Pre-split bf16 images: 0:A0hi 1:A0lo 2:A1hi 3:A1lo 4:Bhi 5:Blo
__device__ __nv_bfloat16 g_pre[6][512 * HDIM];

// ---------------------------------------------------------------------------
union Pack8 { __nv_bfloat16 h[8]; uint4 v; };

__device__ __forceinline__ void split8(const float* s, uint4& hi, uint4& lo) {
    Pack8 ph, pl;
#pragma unroll
    for (int t = 0; t < 8; t++) {
        __nv_bfloat16 h = __float2bfloat16(s[t]);
        ph.h[t] = h;
        pl.h[t] = __float2bfloat16(s[t] - __bfloat162float(h));
    }
    hi = ph.v; lo = pl.v;
}

__global__ void prep_kernel(const float* __restrict__ x,
                            const float* __restrict__ W)
{
    int gid = blockIdx.x * blockDim.x + threadIdx.x;
    if (gid >= 512 * (HDIM / 8)) return;
    int i  = gid / (HDIM / 8);
    int k0 = (gid % (HDIM / 8)) * 8;

    float4 x0 = *(const float4*)(x + (size_t)i * HDIM + k0);
    float4 x1 = *(const float4*)(x + (size_t)i * HDIM + k0 + 4);
    float4 wa0 = *(const float4*)(W + k0);
    float4 wa1 = *(const float4*)(W + k0 + 4);
    float4 wb0 = *(const float4*)(W + 1536 + k0);
    float4 wb1 = *(const float4*)(W + 1536 + k0 + 4);

    float xs[8] = {x0.x, x0.y, x0.z, x0.w, x1.x, x1.y, x1.z, x1.w};
    float w0[8] = {wa0.x, wa0.y, wa0.z, wa0.w, wa1.x, wa1.y, wa1.z, wa1.w};
    float w1[8] = {wb0.x, wb0.y, wb0.z, wb0.w, wb1.x, wb1.y, wb1.z, wb1.w};
    float a0[8], a1[8];
#pragma unroll
    for (int t = 0; t < 8; t++) { a0[t] = xs[t] * w0[t]; a1[t] = xs[t] * w1[t]; }

    uint4 h, l;
    size_t off = (size_t)i * HDIM + k0;
    split8(a0, h, l);
    *(uint4*)(&g_pre[0][off]) = h;  *(uint4*)(&g_pre[1][off]) = l;
    split8(a1, h, l);
    *(uint4*)(&g_pre[2][off]) = h;  *(uint4*)(&g_pre[3][off]) = l;
    split8(xs, h, l);
    *(uint4*)(&g_pre[4][off]) = h;  *(uint4*)(&g_pre[5][off]) = l;
}

// ---------------------------------------------------------------------------
__device__ __forceinline__ uint32_t smem_u32(const void* p) {
    uint32_t a;
    asm("{ .reg .u64 t; cvta.to.shared.u64 t, %1; cvt.u32.u64 %0, t; }"
        : "=r"(a) : "l"(p));
    return a;
}

__device__ __forceinline__ void cp16(uint32_t dst, const void* src) {
    asm volatile("cp.async.cg.shared.global [%0], [%1], 16;"
                 :: "r"(dst), "l"(src) : "memory");
}

__device__ __forceinline__ void ldsm4(uint32_t* r, uint32_t addr) {
    asm volatile("ldmatrix.sync.aligned.m8n8.x4.shared.b16 {%0,%1,%2,%3}, [%4];"
                 : "=r"(r[0]), "=r"(r[1]), "=r"(r[2]), "=r"(r[3]) : "r"(addr));
}

__device__ __forceinline__ void mma16816(float* c, const uint32_t* a,
                                         uint32_t b0, uint32_t b1) {
    asm volatile(
        "mma.sync.aligned.m16n8k16.row.col.f32.bf16.bf16.f32 "
        "{%0,%1,%2,%3}, {%4,%5,%6,%7}, {%8,%9}, {%0,%1,%2,%3};"
        : "+f"(c[0]), "+f"(c[1]), "+f"(c[2]), "+f"(c[3])
        : "r"(a[0]), "r"(a[1]), "r"(a[2]), "r"(a[3]), "r"(b0), "r"(b1));
}

__device__ __forceinline__ void grp_bar(int id) {
    asm volatile("bar.sync %0, 128;" :: "r"(id) : "memory");
}

__global__ void __launch_bounds__(256, 1)
pairwise_mma_kernel(const float* __restrict__ bias, float* __restrict__ out)
{
    // Triangular decode: blockIdx.x in [0,136) -> (bi, bj), bj >= bi
    int t = blockIdx.x;
    int bi = 0;
    while (t >= 16 - bi) { t -= 16 - bi; bi++; }
    const int bj = bi + t;

    extern __shared__ __align__(16) char smem[];
    const uint32_t sbase = smem_u32(smem);

    const int tid  = threadIdx.x;
    const int grp  = tid >> 7;        // K-group 0/1
    const int gtid = tid & 127;
    const int wid  = gtid >> 5;       // warp within group
    const int lane = tid & 31;
    const int wm = wid >> 1;          // warp row (0..1) of 16
    const int wn = wid & 1;           // warp col (0..1) of 16

    const __nv_bfloat16* src[NTILE];
    src[0] = &g_pre[0][(size_t)(bi * 32) * HDIM];
    src[1] = &g_pre[1][(size_t)(bi * 32) * HDIM];
    src[2] = &g_pre[2][(size_t)(bi * 32) * HDIM];
    src[3] = &g_pre[3][(size_t)(bi * 32) * HDIM];
    src[4] = &g_pre[4][(size_t)(bj * 32) * HDIM];
    src[5] = &g_pre[5][(size_t)(bj * 32) * HDIM];

    const uint32_t gb = sbase + grp * GRP_B;
    const int lrow = gtid >> 2;       // 0..31
    const int lc   = gtid & 3;        // 16B chunk within 64B row
    const int kofs = grp * NKCG;      // this group's first chunk

    auto issue = [&](int kc, int sl) {
        const uint32_t dbase = gb + sl * STAGE_B + lrow * ROW_B + lc * 16;
        const int kcol = (kofs + kc) * KC + lc * 8;
#pragma unroll
        for (int q = 0; q < NTILE; q++)
            cp16(dbase + q * TILE_B, src[q] + (size_t)lrow * HDIM + kcol);
    };

    // Per-channel, three independent split chains: 0=hh, 1=hl, 2=lh
    float acc0[3][2][4] = {};
    float acc1[3][2][4] = {};

    const uint32_t arow = (uint32_t)(wm * 16 + (lane & 15)) * ROW_B
                        + ((lane >> 4) << 4);
    const uint32_t brow = (uint32_t)(wn * 16 + (lane & 15)) * ROW_B
                        + ((lane >> 4) << 4);

    auto compute = [&](int sl) {
        const uint32_t tb = gb + sl * STAGE_B;
#pragma unroll
        for (int h = 0; h < 2; h++) {           // two k16 slices of k32
            uint32_t a0h[4], a0l[4], a1h[4], a1l[4], bh[4], bl[4];
            ldsm4(a0h, tb + 0 * TILE_B + arow + h * 32);
            ldsm4(a0l, tb + 1 * TILE_B + arow + h * 32);
            ldsm4(a1h, tb + 2 * TILE_B + arow + h * 32);
            ldsm4(a1l, tb + 3 * TILE_B + arow + h * 32);
            ldsm4(bh,  tb + 4 * TILE_B + brow + h * 32);
            ldsm4(bl,  tb + 5 * TILE_B + brow + h * 32);
#pragma unroll
            for (int nf = 0; nf < 2; nf++) {
                mma16816(acc0[0][nf], a0h, bh[nf], bh[nf + 2]);
                mma16816(acc1[0][nf], a1h, bh[nf], bh[nf + 2]);
                mma16816(acc0[1][nf], a0h, bl[nf], bl[nf + 2]);
                mma16816(acc1[1][nf], a1h, bl[nf], bl[nf + 2]);
                mma16816(acc0[2][nf], a0l, bh[nf], bh[nf + 2]);
                mma16816(acc1[2][nf], a1l, bh[nf], bh[nf + 2]);
            }
        }
    };

    // ---- per-group 2-stage cp.async pipeline over 12 chunks ----
    const int barid = grp + 1;
    issue(0, 0);
    asm volatile("cp.async.commit_group;" ::: "memory");
    issue(1, 1);
    asm volatile("cp.async.commit_group;" ::: "memory");

#pragma unroll 1
    for (int kc = 0; kc < NKCG; kc++) {
        if (kc < NKCG - 1)
            asm volatile("cp.async.wait_group 1;" ::: "memory");
        else
            asm volatile("cp.async.wait_group 0;" ::: "memory");
        grp_bar(barid);
        compute(kc & 1);
        grp_bar(barid);
        if (kc + 2 < NKCG) {
            issue(kc + 2, kc & 1);
            asm volatile("cp.async.commit_group;" ::: "memory");
        }
    }

    // ---- combine the two K-halves via smem, then coalesced STG ----
    float* part = (float*)(smem + PART_OFF);
    float* fin  = (float*)smem;

    if (grp == 1) {
#pragma unroll
        for (int nf = 0; nf < 2; nf++)
#pragma unroll
            for (int r = 0; r < 4; r++) {
                const int idx = (((gtid * 2 + nf) * 4 + r)) * 2;
                part[idx + 0] = acc0[0][nf][r] + acc0[1][nf][r] + acc0[2][nf][r];
                part[idx + 1] = acc1[0][nf][r] + acc1[1][nf][r] + acc1[2][nf][r];
            }
    }
    __syncthreads();

    if (grp == 0) {
        const float bv0 = bias[0];
        const float bv1 = bias[1];
#pragma unroll
        for (int nf = 0; nf < 2; nf++)
#pragma unroll
            for (int r = 0; r < 4; r++) {
                const int idx = (((gtid * 2 + nf) * 4 + r)) * 2;
                const float v0 = acc0[0][nf][r] + acc0[1][nf][r]
                               + acc0[2][nf][r] + part[idx + 0] + bv0;
                const float v1 = acc1[0][nf][r] + acc1[1][nf][r]
                               + acc1[2][nf][r] + part[idx + 1] + bv1;
                const int ii = wm * 16 + (lane >> 2) + ((r >> 1) << 3);
                const int jj = wn * 16 + nf * 8 + ((lane & 3) << 1) + (r & 1);
                fin[ii * FIN_STRIDE + jj * 2 + 0] = v0;
                fin[ii * FIN_STRIDE + jj * 2 + 1] = v1;
            }
    }
    __syncthreads();

    const int ib = bi * 32;
    const int jb = bj * 32;

    // Direct pass: row ii -> out[(gi-1)][jb..jb+31][ch], contiguous
    {
        const int ii = tid >> 3;
        const int q4 = (tid & 7) * 4;
        const int gi = ib + ii;
        if (gi >= 1 && gi <= 510) {
            float* orow = out + (size_t)(gi - 1) * 1020;
#pragma unroll
            for (int u = 0; u < 4; u++) {
                const int jj = q4 + u;
                const int gj = jb + jj;
                if (gj >= 1 && gj <= 510) {
                    float2 v = *(float2*)(fin + ii * FIN_STRIDE + jj * 2);
                    *(float2*)(orow + (size_t)(gj - 1) * 2) = v;
                }
            }
        }
    }
    // Mirror pass (off-diagonal tiles): row jj -> out[(gj-1)][ib..ib+31][ch]
    if (bi != bj) {
        const int jj = tid >> 3;
        const int q4 = (tid & 7) * 4;
        const int gj = jb + jj;
        if (gj >= 1 && gj <= 510) {
            float* orow = out + (size_t)(gj - 1) * 1020;
#pragma unroll
            for (int u = 0; u < 4; u++) {
                const int ii = q4 + u;
                const int gi = ib + ii;
                if (gi >= 1 && gi <= 510) {
                    float2 v = *(float2*)(fin + ii * FIN_STRIDE + jj * 2);
                    *(float2*)(orow + (size_t)(gi - 1) * 2) = v;
                }
            }
        }
    }
}

// ---------------------------------------------------------------------------
extern "C" void kernel_launch(void* const* d_in, const int* in_sizes, int n_in,
                              void* d_out, int out_size)
{
    const float* x = (const float*)d_in[0];   // (1, 512, 768)
    const float* W = (const float*)d_in[1];   // (2, 1536)
    const float* b = (const float*)d_in[2];   // (2,)
    float* out = (float*)d_out;               // (510, 510, 2)

    cudaFuncSetAttribute(pairwise_mma_kernel,
                         cudaFuncAttributeMaxDynamicSharedMemorySize, SMEM_TOTAL);

    prep_kernel<<<192, 256>>>(x, W);
    pairwise_mma_kernel<<<136, 256, SMEM_TOTAL>>>(b, out);
}